// round 10
// baseline (speedup 1.0000x reference)
#include <cuda_runtime.h>
#include <cuda_fp16.h>
#include <math.h>
#include <stdint.h>

#define BB 4
#define LQ 2048
#define LK 2048
#define DM 1024
#define NH 16
#define DK 64
#define NEGV -1000000000.0f

// Pre-split fp16 hi/lo projected tensors (outputs of proj): [B*LEN, NH*DK]
__device__ __half g_qh[BB * LQ * NH * DK];
__device__ __half g_ql[BB * LQ * NH * DK];
__device__ __half g_kh[BB * LK * NH * DK];
__device__ __half g_kl[BB * LK * NH * DK];
__device__ __half g_vh[BB * LK * NH * DK];
__device__ __half g_vl[BB * LK * NH * DK];

// Pre-split inputs (A operands) and weights for the projection GEMMs.
__device__ __half i_qh[BB * LQ * DM], i_ql[BB * LQ * DM];
__device__ __half i_kh[BB * LK * DM], i_kl[BB * LK * DM];
__device__ __half i_vh[BB * LK * DM], i_vl[BB * LK * DM];
__device__ __half w_qh[NH * DK * DM], w_ql[NH * DK * DM];
__device__ __half w_kh[NH * DK * DM], w_kl[NH * DK * DM];
__device__ __half w_vh[NH * DK * DM], w_vl[NH * DK * DM];

__device__ __forceinline__ uint32_t smem_u32(const void* p) {
    uint32_t a;
    asm("{ .reg .u64 t; cvta.to.shared.u64 t, %1; cvt.u32.u64 %0, t; }"
        : "=r"(a) : "l"(p));
    return a;
}
__device__ __forceinline__ void ldm4(unsigned r[4], uint32_t a) {
    asm volatile("ldmatrix.sync.aligned.m8n8.x4.shared.b16 {%0,%1,%2,%3}, [%4];"
        : "=r"(r[0]), "=r"(r[1]), "=r"(r[2]), "=r"(r[3]) : "r"(a));
}
__device__ __forceinline__ void ldm4t(unsigned r[4], uint32_t a) {
    asm volatile("ldmatrix.sync.aligned.m8n8.x4.trans.shared.b16 {%0,%1,%2,%3}, [%4];"
        : "=r"(r[0]), "=r"(r[1]), "=r"(r[2]), "=r"(r[3]) : "r"(a));
}
__device__ __forceinline__ void mma16(float c[4], const unsigned a[4],
                                      unsigned b0, unsigned b1) {
    asm volatile(
        "mma.sync.aligned.m16n8k16.row.col.f32.f16.f16.f32 "
        "{%0,%1,%2,%3},{%4,%5,%6,%7},{%8,%9},{%0,%1,%2,%3};"
        : "+f"(c[0]), "+f"(c[1]), "+f"(c[2]), "+f"(c[3])
        : "r"(a[0]), "r"(a[1]), "r"(a[2]), "r"(a[3]), "r"(b0), "r"(b1));
}
__device__ __forceinline__ void split2x(float a, float b, uint32_t& hi, uint32_t& lo) {
    __half2 h = __floats2half2_rn(a, b);
    float2 hf = __half22float2(h);
    __half2 l = __floats2half2_rn(a - hf.x, b - hf.y);
    hi = *(uint32_t*)&h;
    lo = *(uint32_t*)&l;
}
__device__ __forceinline__ uint32_t pack_h2(float a, float b) {
    __half2 h = __floats2half2_rn(a, b);
    return *(uint32_t*)&h;
}
#define CP16(dst, src) \
    asm volatile("cp.async.cg.shared.global [%0], [%1], 16;" \
                 :: "r"(dst), "l"(src) : "memory")
#define CPCOMMIT() asm volatile("cp.async.commit_group;" ::: "memory")
#define CPWAIT0()  asm volatile("cp.async.wait_group 0;" ::: "memory")

// ---------------------------------------------------------------------------
// Pre-split: fp32 inputs + weights -> fp16 hi/lo pairs. DRAM-bound, ~35us.
// ---------------------------------------------------------------------------
__global__ __launch_bounds__(256) void presplit(
    const float* __restrict__ Qin, const float* __restrict__ Kin,
    const float* __restrict__ Vin,
    const float* __restrict__ Wq, const float* __restrict__ Wk,
    const float* __restrict__ Wv)
{
    const float *A, *W;
    __half *ah, *al, *wh, *wl;
    if (blockIdx.z == 0)      { A = Qin; W = Wq; ah = i_qh; al = i_ql; wh = w_qh; wl = w_ql; }
    else if (blockIdx.z == 1) { A = Kin; W = Wk; ah = i_kh; al = i_kl; wh = w_kh; wl = w_kl; }
    else                      { A = Vin; W = Wv; ah = i_vh; al = i_vl; wh = w_vh; wl = w_vl; }

    const int stride = gridDim.x * blockDim.x;
    const int t0 = blockIdx.x * blockDim.x + threadIdx.x;

    const int NA = BB * LQ * DM / 4;      // float4 count for A
    for (int idx = t0; idx < NA; idx += stride) {
        float4 v = ((const float4*)A)[idx];
        uint32_t h0, l0, h1, l1;
        split2x(v.x, v.y, h0, l0);
        split2x(v.z, v.w, h1, l1);
        ((uint2*)ah)[idx] = make_uint2(h0, h1);
        ((uint2*)al)[idx] = make_uint2(l0, l1);
    }
    const int NW = NH * DK * DM / 4;      // float4 count for W
    for (int idx = t0; idx < NW; idx += stride) {
        float4 v = ((const float4*)W)[idx];
        uint32_t h0, l0, h1, l1;
        split2x(v.x, v.y, h0, l0);
        split2x(v.z, v.w, h1, l1);
        ((uint2*)wh)[idx] = make_uint2(h0, h1);
        ((uint2*)wl)[idx] = make_uint2(l0, l1);
    }
}

// ---------------------------------------------------------------------------
// Projection GEMM from pre-split halves, cp.async double-buffered.
// z = 0:Q (scale 1/8), 1:K, 2:V. BM=128 BN=64 BK=32, 3-term fp16 HMMA.
// Dynamic smem: Ah/Al [2][128][40], Wh/Wl [2][64][40] = 61440 B.
// Copy geometry (FIXED vs R9): CP16 moves 8 halves; each thread owns a
// 16-half span -> two CP16s 16 bytes apart per array.
// ---------------------------------------------------------------------------
#define PA_STRIDE 5120   // halves per A buffer (128*40)
#define PW_STRIDE 2560   // halves per W buffer (64*40)

__global__ __launch_bounds__(256, 2) void proj_hmma(
    const float* __restrict__ bq, const float* __restrict__ bv)
{
    const __half *Agh, *Agl, *Wgh, *Wgl;
    const float* bias;
    __half *Ch, *Cl;
    float scale;
    if (blockIdx.z == 0)      { Agh = i_qh; Agl = i_ql; Wgh = w_qh; Wgl = w_ql;
                                bias = bq;      Ch = g_qh; Cl = g_ql; scale = 0.125f; }
    else if (blockIdx.z == 1) { Agh = i_kh; Agl = i_kl; Wgh = w_kh; Wgl = w_kl;
                                bias = nullptr; Ch = g_kh; Cl = g_kl; scale = 1.f; }
    else                      { Agh = i_vh; Agl = i_vl; Wgh = w_vh; Wgl = w_vl;
                                bias = bv;      Ch = g_vh; Cl = g_vl; scale = 1.f; }

    extern __shared__ char smraw[];
    __half* Ah = (__half*)smraw;                 // [2][128][40]
    __half* Al = Ah + 2 * PA_STRIDE;
    __half* Wh = Al + 2 * PA_STRIDE;             // [2][64][40]
    __half* Wl = Wh + 2 * PW_STRIDE;

    const int tid = threadIdx.x, warp = tid >> 5, lane = tid & 31;
    const int g = lane >> 2, tg = lane & 3;
    const int wm = warp & 3, wn = warp >> 2;
    const int bm = blockIdx.y * 128, bn = blockIdx.x * 64;
    const int lrow = lane & 15, lcol8 = (lane >> 4) << 3;

    // copy geometry: each thread owns 16 halves (two 8-half CP16 chunks)
    const int arow = tid >> 1, acol = (tid & 1) * 16;           // A rows 0..127
    const int wrow = (tid & 127) >> 1, wcol = (tid & 1) * 16;   // W rows 0..63
    const bool whalf = tid < 128;

    float acc[2][4][4];
#pragma unroll
    for (int i = 0; i < 2; ++i)
#pragma unroll
        for (int j = 0; j < 4; ++j)
#pragma unroll
            for (int t = 0; t < 4; ++t) acc[i][j][t] = 0.f;

#define PROJ_COPY(BUF, K0) do {                                               \
    uint32_t da = smem_u32(Ah + (BUF) * PA_STRIDE + arow * 40 + acol);        \
    const __half* sa_h = Agh + (size_t)(bm + arow) * DM + (K0) + acol;        \
    CP16(da, sa_h);                                                           \
    CP16(da + 16, sa_h + 8);                                                  \
    uint32_t dal = smem_u32(Al + (BUF) * PA_STRIDE + arow * 40 + acol);       \
    const __half* sa_l = Agl + (size_t)(bm + arow) * DM + (K0) + acol;        \
    CP16(dal, sa_l);                                                          \
    CP16(dal + 16, sa_l + 8);                                                 \
    if (whalf) {                                                              \
        uint32_t dw = smem_u32(Wh + (BUF) * PW_STRIDE + wrow * 40 + wcol);    \
        const __half* sw = Wgh + (size_t)(bn + wrow) * DM + (K0) + wcol;      \
        CP16(dw, sw);                                                         \
        CP16(dw + 16, sw + 8);                                                \
    } else {                                                                  \
        uint32_t dw = smem_u32(Wl + (BUF) * PW_STRIDE + wrow * 40 + wcol);    \
        const __half* sw = Wgl + (size_t)(bn + wrow) * DM + (K0) + wcol;      \
        CP16(dw, sw);                                                         \
        CP16(dw + 16, sw + 8);                                                \
    }                                                                         \
    CPCOMMIT();                                                               \
} while (0)

#define PROJ_STEP(BUF, K0) do {                                               \
    CPWAIT0();                                                                \
    __syncthreads();                                                          \
    if ((K0) + 32 < DM) PROJ_COPY((BUF) ^ 1, (K0) + 32);                      \
    const uint32_t ahb = smem_u32(Ah + (BUF) * PA_STRIDE);                    \
    const uint32_t alb = smem_u32(Al + (BUF) * PA_STRIDE);                    \
    const uint32_t whb = smem_u32(Wh + (BUF) * PW_STRIDE);                    \
    const uint32_t wlb = smem_u32(Wl + (BUF) * PW_STRIDE);                    \
    _Pragma("unroll")                                                         \
    for (int kk = 0; kk < 32; kk += 16) {                                     \
        unsigned a_h[2][4], a_l[2][4], b_h[2][4], b_l[2][4];                  \
        _Pragma("unroll")                                                     \
        for (int mf = 0; mf < 2; ++mf) {                                      \
            uint32_t off = (uint32_t)((wm * 32 + mf * 16 + lrow) * 40 + kk + lcol8) * 2; \
            ldm4(a_h[mf], ahb + off);                                         \
            ldm4(a_l[mf], alb + off);                                         \
        }                                                                     \
        _Pragma("unroll")                                                     \
        for (int nh = 0; nh < 2; ++nh) {                                      \
            uint32_t off = (uint32_t)((wn * 32 + nh * 16 + lrow) * 40 + kk + lcol8) * 2; \
            ldm4(b_h[nh], whb + off);                                         \
            ldm4(b_l[nh], wlb + off);                                         \
        }                                                                     \
        _Pragma("unroll")                                                     \
        for (int mf = 0; mf < 2; ++mf)                                        \
            _Pragma("unroll")                                                 \
            for (int nh = 0; nh < 2; ++nh)                                    \
                _Pragma("unroll")                                             \
                for (int j = 0; j < 2; ++j) {                                 \
                    int nf = nh * 2 + j;                                      \
                    mma16(acc[mf][nf], a_h[mf], b_h[nh][j], b_h[nh][2 + j]);  \
                    mma16(acc[mf][nf], a_l[mf], b_h[nh][j], b_h[nh][2 + j]);  \
                    mma16(acc[mf][nf], a_h[mf], b_l[nh][j], b_l[nh][2 + j]);  \
                }                                                             \
    }                                                                         \
} while (0)

    PROJ_COPY(0, 0);
    for (int k0 = 0; k0 < DM; k0 += 64) {
        PROJ_STEP(0, k0);
        PROJ_STEP(1, k0 + 32);
    }
#undef PROJ_STEP
#undef PROJ_COPY

    // Epilogue: bias + scale, store pre-split hi/lo.
#pragma unroll
    for (int mf = 0; mf < 2; ++mf)
#pragma unroll
        for (int nf = 0; nf < 4; ++nf) {
            int r = bm + wm * 32 + mf * 16 + g;
            int c = bn + wn * 32 + (nf >> 1) * 16 + (nf & 1) * 8 + 2 * tg;
            float b0 = 0.f, b1 = 0.f;
            if (bias) { float2 bb = *(const float2*)(bias + c); b0 = bb.x; b1 = bb.y; }
            uint32_t hi, lo;
            split2x((acc[mf][nf][0] + b0) * scale, (acc[mf][nf][1] + b1) * scale, hi, lo);
            *(uint32_t*)(Ch + (size_t)r * (NH * DK) + c) = hi;
            *(uint32_t*)(Cl + (size_t)r * (NH * DK) + c) = lo;
            split2x((acc[mf][nf][2] + b0) * scale, (acc[mf][nf][3] + b1) * scale, hi, lo);
            *(uint32_t*)(Ch + (size_t)(r + 8) * (NH * DK) + c) = hi;
            *(uint32_t*)(Cl + (size_t)(r + 8) * (NH * DK) + c) = lo;
        }
}

// ---------------------------------------------------------------------------
// Flash attention (unchanged from R8): pre-split inputs, cp.async double
// buffering, register softmax, S 3-term, PV 2-term.
// ---------------------------------------------------------------------------
__global__ __launch_bounds__(256, 2) void attn_reg(
    const int* __restrict__ mask, float* __restrict__ out)
{
    __shared__ __half Ksh[2][32][72], Ksl[2][32][72];
    __shared__ __half Vsh[2][32][72], Vsl[2][32][72];
    __shared__ uint32_t mbw[2];

    const int tid = threadIdx.x, warp = tid >> 5, lane = tid & 31;
    const int g = lane >> 2, tg = lane & 3;
    const int b = blockIdx.z, h = blockIdx.y;
    const int q0 = blockIdx.x * 128;

    const int lrow = lane & 15, lcol8 = (lane >> 4) << 3;
    const int kvr  = (lane & 7) + ((lane >> 4) << 3);
    const int dcol = ((lane >> 3) & 1) * 8;
    const int cr = tid >> 3, cc = (tid & 7) * 8;

    unsigned qfh[4][4], qfl[4][4];
    {
        size_t r0 = (size_t)(b * LQ + q0 + warp * 16 + g) * (NH * DK) + h * DK;
        size_t r1 = r0 + (size_t)8 * (NH * DK);
#pragma unroll
        for (int kk = 0; kk < 4; ++kk) {
            int c = kk * 16 + 2 * tg;
            qfh[kk][0] = *(const uint32_t*)(g_qh + r0 + c);
            qfh[kk][1] = *(const uint32_t*)(g_qh + r1 + c);
            qfh[kk][2] = *(const uint32_t*)(g_qh + r0 + c + 8);
            qfh[kk][3] = *(const uint32_t*)(g_qh + r1 + c + 8);
            qfl[kk][0] = *(const uint32_t*)(g_ql + r0 + c);
            qfl[kk][1] = *(const uint32_t*)(g_ql + r1 + c);
            qfl[kk][2] = *(const uint32_t*)(g_ql + r0 + c + 8);
            qfl[kk][3] = *(const uint32_t*)(g_ql + r1 + c + 8);
        }
    }

    float o[8][4];
#pragma unroll
    for (int i = 0; i < 8; ++i)
#pragma unroll
        for (int j = 0; j < 4; ++j) o[i][j] = 0.f;
    float mrA = -INFINITY, mrB = -INFINITY, lrA = 0.f, lrB = 0.f;

    {
        size_t goff = (size_t)(b * LK + cr) * (NH * DK) + h * DK + cc;
        CP16(smem_u32(&Ksh[0][cr][cc]), g_kh + goff);
        CP16(smem_u32(&Ksl[0][cr][cc]), g_kl + goff);
        CP16(smem_u32(&Vsh[0][cr][cc]), g_vh + goff);
        CP16(smem_u32(&Vsl[0][cr][cc]), g_vl + goff);
        CPCOMMIT();
        if (warp == 0) {
            uint32_t bal = __ballot_sync(0xffffffffu, mask[b * LK + lane] != 0);
            if (lane == 0) mbw[0] = bal;
        }
    }

#define TILE_STEP(BUF, KT) do {                                               \
    CPWAIT0();                                                                \
    __syncthreads();                                                          \
    if ((KT) + 32 < LK) {                                                     \
        size_t goff = (size_t)(b * LK + (KT) + 32 + cr) * (NH * DK) + h * DK + cc; \
        CP16(smem_u32(&Ksh[(BUF) ^ 1][cr][cc]), g_kh + goff);                 \
        CP16(smem_u32(&Ksl[(BUF) ^ 1][cr][cc]), g_kl + goff);                 \
        CP16(smem_u32(&Vsh[(BUF) ^ 1][cr][cc]), g_vh + goff);                 \
        CP16(smem_u32(&Vsl[(BUF) ^ 1][cr][cc]), g_vl + goff);                 \
        CPCOMMIT();                                                           \
        if (warp == 0) {                                                      \
            uint32_t bal = __ballot_sync(0xffffffffu,                         \
                                mask[b * LK + (KT) + 32 + lane] != 0);        \
            if (lane == 0) mbw[(BUF) ^ 1] = bal;                              \
        }                                                                     \
    }                                                                         \
    const uint32_t mb = mbw[BUF];                                             \
    float sa[4][4];                                                           \
    _Pragma("unroll")                                                         \
    for (int nf = 0; nf < 4; ++nf)                                            \
        { sa[nf][0] = 0.f; sa[nf][1] = 0.f; sa[nf][2] = 0.f; sa[nf][3] = 0.f; } \
    _Pragma("unroll")                                                         \
    for (int kk = 0; kk < 4; ++kk) {                                          \
        _Pragma("unroll")                                                     \
        for (int nh = 0; nh < 2; ++nh) {                                      \
            unsigned kbh[4], kbl[4];                                          \
            uint32_t off = (uint32_t)((nh * 16 + lrow) * 72 + kk * 16 + lcol8) * 2; \
            ldm4(kbh, smem_u32(&Ksh[BUF][0][0]) + off);                       \
            ldm4(kbl, smem_u32(&Ksl[BUF][0][0]) + off);                       \
            _Pragma("unroll")                                                 \
            for (int j = 0; j < 2; ++j) {                                     \
                int nf = nh * 2 + j;                                          \
                mma16(sa[nf], qfh[kk], kbh[j], kbh[2 + j]);                   \
                mma16(sa[nf], qfl[kk], kbh[j], kbh[2 + j]);                   \
                mma16(sa[nf], qfh[kk], kbl[j], kbl[2 + j]);                   \
            }                                                                 \
        }                                                                     \
    }                                                                         \
    float mA = NEGV, mB = NEGV;                                               \
    _Pragma("unroll")                                                         \
    for (int nf = 0; nf < 4; ++nf) {                                          \
        int c0 = nf * 8 + 2 * tg;                                             \
        bool k0 = (mb >> c0) & 1u;                                            \
        bool k1 = (mb >> (c0 + 1)) & 1u;                                      \
        sa[nf][0] = k0 ? sa[nf][0] : NEGV;                                    \
        sa[nf][1] = k1 ? sa[nf][1] : NEGV;                                    \
        sa[nf][2] = k0 ? sa[nf][2] : NEGV;                                    \
        sa[nf][3] = k1 ? sa[nf][3] : NEGV;                                    \
        mA = fmaxf(mA, fmaxf(sa[nf][0], sa[nf][1]));                          \
        mB = fmaxf(mB, fmaxf(sa[nf][2], sa[nf][3]));                          \
    }                                                                         \
    mA = fmaxf(mA, __shfl_xor_sync(0xffffffffu, mA, 1));                      \
    mA = fmaxf(mA, __shfl_xor_sync(0xffffffffu, mA, 2));                      \
    mB = fmaxf(mB, __shfl_xor_sync(0xffffffffu, mB, 1));                      \
    mB = fmaxf(mB, __shfl_xor_sync(0xffffffffu, mB, 2));                      \
    float mnA = fmaxf(mrA, mA), mnB = fmaxf(mrB, mB);                         \
    float alA = __expf(mrA - mnA), alB = __expf(mrB - mnB);                   \
    mrA = mnA; mrB = mnB;                                                     \
    unsigned pah[2][4];                                                       \
    float lsA = 0.f, lsB = 0.f;                                               \
    _Pragma("unroll")                                                         \
    for (int jk = 0; jk < 2; ++jk) {                                          \
        _Pragma("unroll")                                                     \
        for (int t = 0; t < 2; ++t) {                                         \
            int nf = jk * 2 + t;                                              \
            float p0 = __expf(sa[nf][0] - mnA);                               \
            float p1 = __expf(sa[nf][1] - mnA);                               \
            float p2 = __expf(sa[nf][2] - mnB);                               \
            float p3 = __expf(sa[nf][3] - mnB);                               \
            lsA += p0 + p1; lsB += p2 + p3;                                   \
            pah[jk][2 * t]     = pack_h2(p0, p1);                             \
            pah[jk][2 * t + 1] = pack_h2(p2, p3);                             \
        }                                                                     \
    }                                                                         \
    lsA += __shfl_xor_sync(0xffffffffu, lsA, 1);                              \
    lsA += __shfl_xor_sync(0xffffffffu, lsA, 2);                              \
    lsB += __shfl_xor_sync(0xffffffffu, lsB, 1);                              \
    lsB += __shfl_xor_sync(0xffffffffu, lsB, 2);                              \
    lrA = lrA * alA + lsA;                                                    \
    lrB = lrB * alB + lsB;                                                    \
    _Pragma("unroll")                                                         \
    for (int nf = 0; nf < 8; ++nf) {                                          \
        o[nf][0] *= alA; o[nf][1] *= alA;                                     \
        o[nf][2] *= alB; o[nf][3] *= alB;                                     \
    }                                                                         \
    _Pragma("unroll")                                                         \
    for (int jk = 0; jk < 2; ++jk) {                                          \
        _Pragma("unroll")                                                     \
        for (int dh = 0; dh < 4; ++dh) {                                      \
            unsigned vbh[4], vbl[4];                                          \
            uint32_t off = (uint32_t)((jk * 16 + kvr) * 72 + dh * 16 + dcol) * 2; \
            ldm4t(vbh, smem_u32(&Vsh[BUF][0][0]) + off);                      \
            ldm4t(vbl, smem_u32(&Vsl[BUF][0][0]) + off);                      \
            _Pragma("unroll")                                                 \
            for (int j = 0; j < 2; ++j) {                                     \
                int nf = dh * 2 + j;                                          \
                mma16(o[nf], pah[jk], vbh[j], vbh[2 + j]);                    \
                mma16(o[nf], pah[jk], vbl[j], vbl[2 + j]);                    \
            }                                                                 \
        }                                                                     \
    }                                                                         \
} while (0)

    for (int kt = 0; kt < LK; kt += 64) {
        TILE_STEP(0, kt);
        TILE_STEP(1, kt + 32);
    }
#undef TILE_STEP

    {
        float iA = 1.f / lrA, iB = 1.f / lrB;
        float* o0 = out + (size_t)(b * LQ + q0 + warp * 16 + g) * (NH * DK) + h * DK;
        float* o1 = o0 + (size_t)8 * (NH * DK);
#pragma unroll
        for (int nf = 0; nf < 8; ++nf) {
            int c = (nf >> 1) * 16 + (nf & 1) * 8 + 2 * tg;
            *(float2*)(o0 + c) = make_float2(o[nf][0] * iA, o[nf][1] * iA);
            *(float2*)(o1 + c) = make_float2(o[nf][2] * iB, o[nf][3] * iB);
        }
    }
}

// ---------------------------------------------------------------------------
extern "C" void kernel_launch(void* const* d_in, const int* in_sizes, int n_in,
                              void* d_out, int out_size)
{
    const float* Q    = (const float*)d_in[0];
    const float* K    = (const float*)d_in[1];
    const float* V    = (const float*)d_in[2];
    const int*   mask = (const int*)d_in[3];
    const float* Wq   = (const float*)d_in[4];
    const float* bq   = (const float*)d_in[5];
    const float* Wk   = (const float*)d_in[6];
    const float* Wv   = (const float*)d_in[7];
    const float* bv   = (const float*)d_in[8];
    float* out = (float*)d_out;

    const int PROJ_SMEM = (4 * 5120 + 4 * 2560) * 2;  // 61440 B
    cudaFuncSetAttribute(proj_hmma, cudaFuncAttributeMaxDynamicSharedMemorySize,
                         PROJ_SMEM);

    presplit<<<dim3(512, 1, 3), 256>>>(Q, K, V, Wq, Wk, Wv);

    dim3 gproj((NH * DK) / 64, (BB * LQ) / 128, 3);  // (16, 64, 3)
    proj_hmma<<<gproj, 256, PROJ_SMEM>>>(bq, bv);

    dim3 gattn(LQ / 128, NH, BB);  // (16, 16, 4)
    attn_reg<<<gattn, 256>>>(mask, out);
}

// round 11
// speedup vs baseline: 1.0714x; 1.0714x over previous
#include <cuda_runtime.h>
#include <cuda_fp16.h>
#include <math.h>
#include <stdint.h>

#define BB 4
#define LQ 2048
#define LK 2048
#define DM 1024
#define NH 16
#define DK 64
#define NEGV -1000000000.0f

// Pre-split fp16 hi/lo projected tensors: [B*LEN, NH*DK]
__device__ __half g_qh[BB * LQ * NH * DK];
__device__ __half g_ql[BB * LQ * NH * DK];
__device__ __half g_kh[BB * LK * NH * DK];
__device__ __half g_kl[BB * LK * NH * DK];
__device__ __half g_vh[BB * LK * NH * DK];
__device__ __half g_vl[BB * LK * NH * DK];

__device__ __forceinline__ uint32_t smem_u32(const void* p) {
    uint32_t a;
    asm("{ .reg .u64 t; cvta.to.shared.u64 t, %1; cvt.u32.u64 %0, t; }"
        : "=r"(a) : "l"(p));
    return a;
}
__device__ __forceinline__ void ldm4(unsigned r[4], uint32_t a) {
    asm volatile("ldmatrix.sync.aligned.m8n8.x4.shared.b16 {%0,%1,%2,%3}, [%4];"
        : "=r"(r[0]), "=r"(r[1]), "=r"(r[2]), "=r"(r[3]) : "r"(a));
}
__device__ __forceinline__ void ldm4t(unsigned r[4], uint32_t a) {
    asm volatile("ldmatrix.sync.aligned.m8n8.x4.trans.shared.b16 {%0,%1,%2,%3}, [%4];"
        : "=r"(r[0]), "=r"(r[1]), "=r"(r[2]), "=r"(r[3]) : "r"(a));
}
__device__ __forceinline__ void mma16(float c[4], const unsigned a[4],
                                      unsigned b0, unsigned b1) {
    asm volatile(
        "mma.sync.aligned.m16n8k16.row.col.f32.f16.f16.f32 "
        "{%0,%1,%2,%3},{%4,%5,%6,%7},{%8,%9},{%0,%1,%2,%3};"
        : "+f"(c[0]), "+f"(c[1]), "+f"(c[2]), "+f"(c[3])
        : "r"(a[0]), "r"(a[1]), "r"(a[2]), "r"(a[3]), "r"(b0), "r"(b1));
}
__device__ __forceinline__ void split2x(float a, float b, uint32_t& hi, uint32_t& lo) {
    __half2 h = __floats2half2_rn(a, b);
    float2 hf = __half22float2(h);
    __half2 l = __floats2half2_rn(a - hf.x, b - hf.y);
    hi = *(uint32_t*)&h;
    lo = *(uint32_t*)&l;
}
__device__ __forceinline__ uint32_t pack_h2(float a, float b) {
    __half2 h = __floats2half2_rn(a, b);
    return *(uint32_t*)&h;
}
#define CP16(dst, src) \
    asm volatile("cp.async.cg.shared.global [%0], [%1], 16;" \
                 :: "r"(dst), "l"(src) : "memory")
#define CPCOMMIT() asm volatile("cp.async.commit_group;" ::: "memory")
#define CPWAIT0()  asm volatile("cp.async.wait_group 0;" ::: "memory")
#define CPWAIT1()  asm volatile("cp.async.wait_group 1;" ::: "memory")

// ---------------------------------------------------------------------------
// Fused projections (R8 version — proven 563us). z = 0:Q scaled by
// log2(e)/8 (for exp2 softmax), 1:K, 2:V. BM=128 BN=64 BK=32, 3-term HMMA.
// ---------------------------------------------------------------------------
__global__ __launch_bounds__(256, 2) void proj_hmma(
    const float* __restrict__ Qin, const float* __restrict__ Kin,
    const float* __restrict__ Vin,
    const float* __restrict__ Wq, const float* __restrict__ bq,
    const float* __restrict__ Wk,
    const float* __restrict__ Wv, const float* __restrict__ bv)
{
    const float *A, *W, *bias;
    __half *Ch, *Cl;
    float scale;
    if (blockIdx.z == 0)      { A = Qin; W = Wq; bias = bq;      Ch = g_qh; Cl = g_ql;
                                scale = 0.18033688f; }   // (1/8)*log2(e)
    else if (blockIdx.z == 1) { A = Kin; W = Wk; bias = nullptr; Ch = g_kh; Cl = g_kl; scale = 1.f; }
    else                      { A = Vin; W = Wv; bias = bv;      Ch = g_vh; Cl = g_vl; scale = 1.f; }

    __shared__ __half Ah[128][40], Al[128][40];
    __shared__ __half Wh[64][40],  Wl[64][40];

    const int tid = threadIdx.x, warp = tid >> 5, lane = tid & 31;
    const int g = lane >> 2, tg = lane & 3;
    const int wm = warp & 3, wn = warp >> 2;
    const int bm = blockIdx.y * 128, bn = blockIdx.x * 64;

    const uint32_t ah_b = smem_u32(Ah), al_b = smem_u32(Al);
    const uint32_t wh_b = smem_u32(Wh), wl_b = smem_u32(Wl);
    const int lrow = lane & 15, lcol8 = (lane >> 4) << 3;

    float acc[2][4][4];
#pragma unroll
    for (int i = 0; i < 2; ++i)
#pragma unroll
        for (int j = 0; j < 4; ++j)
#pragma unroll
            for (int t = 0; t < 4; ++t) acc[i][j][t] = 0.f;

    for (int k0 = 0; k0 < DM; k0 += 32) {
        __syncthreads();
#pragma unroll
        for (int i = 0; i < 4; ++i) {            // A: 128x32
            int f4 = tid + i * 256;
            int r = f4 >> 3, c4 = (f4 & 7) * 4;
            float4 v = *(const float4*)(A + (size_t)(bm + r) * DM + k0 + c4);
            uint32_t h0, l0, h1, l1;
            split2x(v.x, v.y, h0, l0);
            split2x(v.z, v.w, h1, l1);
            *(uint32_t*)&Ah[r][c4] = h0; *(uint32_t*)&Ah[r][c4 + 2] = h1;
            *(uint32_t*)&Al[r][c4] = l0; *(uint32_t*)&Al[r][c4 + 2] = l1;
        }
#pragma unroll
        for (int i = 0; i < 2; ++i) {            // W: 64x32
            int f4 = tid + i * 256;
            int r = f4 >> 3, c4 = (f4 & 7) * 4;
            float4 v = *(const float4*)(W + (size_t)(bn + r) * DM + k0 + c4);
            uint32_t h0, l0, h1, l1;
            split2x(v.x, v.y, h0, l0);
            split2x(v.z, v.w, h1, l1);
            *(uint32_t*)&Wh[r][c4] = h0; *(uint32_t*)&Wh[r][c4 + 2] = h1;
            *(uint32_t*)&Wl[r][c4] = l0; *(uint32_t*)&Wl[r][c4 + 2] = l1;
        }
        __syncthreads();

#pragma unroll
        for (int kk = 0; kk < 32; kk += 16) {
            unsigned a_h[2][4], a_l[2][4], b_h[2][4], b_l[2][4];
#pragma unroll
            for (int mf = 0; mf < 2; ++mf) {
                uint32_t off = (uint32_t)((wm * 32 + mf * 16 + lrow) * 40 + kk + lcol8) * 2;
                ldm4(a_h[mf], ah_b + off);
                ldm4(a_l[mf], al_b + off);
            }
#pragma unroll
            for (int nh = 0; nh < 2; ++nh) {
                uint32_t off = (uint32_t)((wn * 32 + nh * 16 + lrow) * 40 + kk + lcol8) * 2;
                ldm4(b_h[nh], wh_b + off);
                ldm4(b_l[nh], wl_b + off);
            }
#pragma unroll
            for (int mf = 0; mf < 2; ++mf)
#pragma unroll
                for (int nh = 0; nh < 2; ++nh)
#pragma unroll
                    for (int j = 0; j < 2; ++j) {
                        int nf = nh * 2 + j;
                        mma16(acc[mf][nf], a_h[mf], b_h[nh][j], b_h[nh][2 + j]);
                        mma16(acc[mf][nf], a_l[mf], b_h[nh][j], b_h[nh][2 + j]);
                        mma16(acc[mf][nf], a_h[mf], b_l[nh][j], b_l[nh][2 + j]);
                    }
        }
    }

#pragma unroll
    for (int mf = 0; mf < 2; ++mf)
#pragma unroll
        for (int nf = 0; nf < 4; ++nf) {
            int r = bm + wm * 32 + mf * 16 + g;
            int c = bn + wn * 32 + (nf >> 1) * 16 + (nf & 1) * 8 + 2 * tg;
            float b0 = 0.f, b1 = 0.f;
            if (bias) { float2 bb = *(const float2*)(bias + c); b0 = bb.x; b1 = bb.y; }
            uint32_t hi, lo;
            split2x((acc[mf][nf][0] + b0) * scale, (acc[mf][nf][1] + b1) * scale, hi, lo);
            *(uint32_t*)(Ch + (size_t)r * (NH * DK) + c) = hi;
            *(uint32_t*)(Cl + (size_t)r * (NH * DK) + c) = lo;
            split2x((acc[mf][nf][2] + b0) * scale, (acc[mf][nf][3] + b1) * scale, hi, lo);
            *(uint32_t*)(Ch + (size_t)(r + 8) * (NH * DK) + c) = hi;
            *(uint32_t*)(Cl + (size_t)(r + 8) * (NH * DK) + c) = lo;
        }
}

// ---------------------------------------------------------------------------
// Flash attention, cross-tile software pipeline:
//   iter t: [sync; prefetch t+2 -> b2; wait copy(t+1); sync]
//           S(t+1) MMAs (independent) overlap softmax(t) ALU; then PV(t).
// 3 KV buffers; Q hi/lo staged in smem; exp2-domain softmax (scale folded
// into Q at projection). S 3-term, PV 2-term (same numerics as R8).
// ---------------------------------------------------------------------------
// smem layout (halves): QH 0, QL 9216, KH 18432+B*2304, KL 25344+B*2304,
//                       VH 32256+B*2304, VL 39168+B*2304; MBW @ byte 92160.
#define ATTN_SMEM 92192
#define BUFB 4608   // bytes per buffer step (2304 halves)

__global__ __launch_bounds__(256, 2) void attn_pipe(
    const int* __restrict__ mask, float* __restrict__ out)
{
    extern __shared__ __half sm[];
    const uint32_t smb = smem_u32(sm);
    const uint32_t qh_base = smb;
    const uint32_t ql_base = smb + 9216 * 2;
    const uint32_t kh0 = smb + 18432 * 2;
    const uint32_t kl0 = smb + 25344 * 2;
    const uint32_t vh0 = smb + 32256 * 2;
    const uint32_t vl0 = smb + 39168 * 2;
    uint32_t* MBW = (uint32_t*)((char*)sm + 92160);

    const int tid = threadIdx.x, warp = tid >> 5, lane = tid & 31;
    const int g = lane >> 2, tg = lane & 3;
    const int b = blockIdx.z, h = blockIdx.y;
    const int q0 = blockIdx.x * 128;

    const int lrow = lane & 15, lcol8 = (lane >> 4) << 3;
    const int kvr  = (lane & 7) + ((lane >> 4) << 3);   // trans-ldmatrix row
    const int dcol = ((lane >> 3) & 1) * 8;
    const int cr = tid >> 3, cc = (tid & 7) * 8;
    const uint32_t cpo = (uint32_t)(cr * 72 + cc) * 2;  // KV copy dst offset

    float o[8][4];
#pragma unroll
    for (int i = 0; i < 8; ++i)
#pragma unroll
        for (int j = 0; j < 4; ++j) o[i][j] = 0.f;
    float mrA = -INFINITY, mrB = -INFINITY, lrA = 0.f, lrB = 0.f;
    float sa[4][4], sa_n[4][4];

    // ---- prologue: stage Q (hi/lo) + KV tiles 0,1; masks 0,1 ----
    {
        int qrow = tid >> 1, qcb = (tid & 1) * 32;
        size_t qg = (size_t)(b * LQ + q0 + qrow) * (NH * DK) + h * DK + qcb;
        uint32_t qdh = qh_base + (uint32_t)(qrow * 72 + qcb) * 2;
        uint32_t qdl = ql_base + (uint32_t)(qrow * 72 + qcb) * 2;
#pragma unroll
        for (int j = 0; j < 4; ++j) {
            CP16(qdh + j * 16, g_qh + qg + j * 8);
            CP16(qdl + j * 16, g_ql + qg + j * 8);
        }
        size_t g0 = (size_t)(b * LK + cr) * (NH * DK) + h * DK + cc;
        CP16(kh0 + cpo, g_kh + g0); CP16(kl0 + cpo, g_kl + g0);
        CP16(vh0 + cpo, g_vh + g0); CP16(vl0 + cpo, g_vl + g0);
        size_t g1 = (size_t)(b * LK + 32 + cr) * (NH * DK) + h * DK + cc;
        CP16(kh0 + BUFB + cpo, g_kh + g1); CP16(kl0 + BUFB + cpo, g_kl + g1);
        CP16(vh0 + BUFB + cpo, g_vh + g1); CP16(vl0 + BUFB + cpo, g_vl + g1);
        CPCOMMIT();
        if (warp == 0) {
            uint32_t b0 = __ballot_sync(0xffffffffu, mask[b * LK + lane] != 0);
            uint32_t b1 = __ballot_sync(0xffffffffu, mask[b * LK + 32 + lane] != 0);
            if (lane == 0) { MBW[0] = b0; MBW[1] = b1; }
        }
        CPWAIT0();
        __syncthreads();
    }

// S-MMAs for one tile from buffer BIDX into DST (Q from smem).
#define S_MMA(DST, BIDX) do {                                                 \
    _Pragma("unroll")                                                         \
    for (int nf = 0; nf < 4; ++nf)                                            \
        { DST[nf][0]=0.f; DST[nf][1]=0.f; DST[nf][2]=0.f; DST[nf][3]=0.f; }   \
    _Pragma("unroll")                                                         \
    for (int kk = 0; kk < 4; ++kk) {                                          \
        unsigned qa_h[4], qa_l[4];                                            \
        uint32_t qoff = (uint32_t)((warp * 16 + lrow) * 72 + kk * 16 + lcol8) * 2; \
        ldm4(qa_h, qh_base + qoff);                                           \
        ldm4(qa_l, ql_base + qoff);                                           \
        _Pragma("unroll")                                                     \
        for (int nh = 0; nh < 2; ++nh) {                                      \
            unsigned kbh[4], kbl[4];                                          \
            uint32_t koff = (uint32_t)((nh * 16 + lrow) * 72 + kk * 16 + lcol8) * 2; \
            ldm4(kbh, kh0 + (BIDX) * BUFB + koff);                            \
            ldm4(kbl, kl0 + (BIDX) * BUFB + koff);                            \
            _Pragma("unroll")                                                 \
            for (int j = 0; j < 2; ++j) {                                     \
                int nf = nh * 2 + j;                                          \
                mma16(DST[nf], qa_h, kbh[j], kbh[2 + j]);                     \
                mma16(DST[nf], qa_l, kbh[j], kbh[2 + j]);                     \
                mma16(DST[nf], qa_h, kbl[j], kbl[2 + j]);                     \
            }                                                                 \
        }                                                                     \
    }                                                                         \
} while (0)

// softmax on sa (exp2 domain) + O rescale + PV from buffer BIDX.
#define SOFTMAX_PV(BIDX) do {                                                 \
    const uint32_t mb = MBW[BIDX];                                            \
    float mA = NEGV, mBv = NEGV;                                              \
    _Pragma("unroll")                                                         \
    for (int nf = 0; nf < 4; ++nf) {                                          \
        int c0 = nf * 8 + 2 * tg;                                             \
        bool k0 = (mb >> c0) & 1u;                                            \
        bool k1 = (mb >> (c0 + 1)) & 1u;                                      \
        sa[nf][0] = k0 ? sa[nf][0] : NEGV;                                    \
        sa[nf][1] = k1 ? sa[nf][1] : NEGV;                                    \
        sa[nf][2] = k0 ? sa[nf][2] : NEGV;                                    \
        sa[nf][3] = k1 ? sa[nf][3] : NEGV;                                    \
        mA = fmaxf(mA, fmaxf(sa[nf][0], sa[nf][1]));                          \
        mBv = fmaxf(mBv, fmaxf(sa[nf][2], sa[nf][3]));                        \
    }                                                                         \
    mA = fmaxf(mA, __shfl_xor_sync(0xffffffffu, mA, 1));                      \
    mA = fmaxf(mA, __shfl_xor_sync(0xffffffffu, mA, 2));                      \
    mBv = fmaxf(mBv, __shfl_xor_sync(0xffffffffu, mBv, 1));                   \
    mBv = fmaxf(mBv, __shfl_xor_sync(0xffffffffu, mBv, 2));                   \
    float mnA = fmaxf(mrA, mA), mnB = fmaxf(mrB, mBv);                        \
    float alA = exp2f(mrA - mnA), alB = exp2f(mrB - mnB);                     \
    mrA = mnA; mrB = mnB;                                                     \
    unsigned pah[2][4];                                                       \
    float lsA = 0.f, lsB = 0.f;                                               \
    _Pragma("unroll")                                                         \
    for (int jk = 0; jk < 2; ++jk) {                                          \
        _Pragma("unroll")                                                     \
        for (int t2 = 0; t2 < 2; ++t2) {                                      \
            int nf = jk * 2 + t2;                                             \
            float p0 = exp2f(sa[nf][0] - mnA);                                \
            float p1 = exp2f(sa[nf][1] - mnA);                                \
            float p2 = exp2f(sa[nf][2] - mnB);                                \
            float p3 = exp2f(sa[nf][3] - mnB);                                \
            lsA += p0 + p1; lsB += p2 + p3;                                   \
            pah[jk][2 * t2]     = pack_h2(p0, p1);                            \
            pah[jk][2 * t2 + 1] = pack_h2(p2, p3);                            \
        }                                                                     \
    }                                                                         \
    lsA += __shfl_xor_sync(0xffffffffu, lsA, 1);                              \
    lsA += __shfl_xor_sync(0xffffffffu, lsA, 2);                              \
    lsB += __shfl_xor_sync(0xffffffffu, lsB, 1);                              \
    lsB += __shfl_xor_sync(0xffffffffu, lsB, 2);                              \
    lrA = lrA * alA + lsA;                                                    \
    lrB = lrB * alB + lsB;                                                    \
    _Pragma("unroll")                                                         \
    for (int nf = 0; nf < 8; ++nf) {                                          \
        o[nf][0] *= alA; o[nf][1] *= alA;                                     \
        o[nf][2] *= alB; o[nf][3] *= alB;                                     \
    }                                                                         \
    _Pragma("unroll")                                                         \
    for (int jk = 0; jk < 2; ++jk) {                                          \
        _Pragma("unroll")                                                     \
        for (int dh = 0; dh < 4; ++dh) {                                      \
            unsigned vbh[4], vbl[4];                                          \
            uint32_t voff = (uint32_t)((jk * 16 + kvr) * 72 + dh * 16 + dcol) * 2; \
            ldm4t(vbh, vh0 + (BIDX) * BUFB + voff);                           \
            ldm4t(vbl, vl0 + (BIDX) * BUFB + voff);                           \
            _Pragma("unroll")                                                 \
            for (int j = 0; j < 2; ++j) {                                     \
                int nf = dh * 2 + j;                                          \
                mma16(o[nf], pah[jk], vbh[j], vbh[2 + j]);                    \
                mma16(o[nf], pah[jk], vbl[j], vbl[2 + j]);                    \
            }                                                                 \
        }                                                                     \
    }                                                                         \
} while (0)

// One pipelined iteration at tile T with buffers (B=T%3, B1, B2).
#define ITER(T, B, B1, B2) do {                                               \
    __syncthreads();  /* all warps done reading buffer B2 (tile T-1) */       \
    if ((T) + 2 < 64) {                                                       \
        int ktt = ((T) + 2) * 32;                                             \
        size_t goff = (size_t)(b * LK + ktt + cr) * (NH * DK) + h * DK + cc;  \
        CP16(kh0 + (B2) * BUFB + cpo, g_kh + goff);                           \
        CP16(kl0 + (B2) * BUFB + cpo, g_kl + goff);                           \
        CP16(vh0 + (B2) * BUFB + cpo, g_vh + goff);                           \
        CP16(vl0 + (B2) * BUFB + cpo, g_vl + goff);                           \
        if (warp == 0) {                                                      \
            uint32_t bal = __ballot_sync(0xffffffffu,                         \
                                mask[b * LK + ktt + lane] != 0);              \
            if (lane == 0) MBW[B2] = bal;                                     \
        }                                                                     \
    }                                                                         \
    CPCOMMIT();   /* unconditional: keeps group counting uniform */           \
    CPWAIT1();    /* copy(T+1) complete */                                    \
    __syncthreads();                                                          \
    S_MMA(sa_n, B1);     /* independent tensor work for tile T+1 */           \
    SOFTMAX_PV(B);       /* ALU chain of tile T overlaps S(T+1) MMAs */       \
    _Pragma("unroll")                                                         \
    for (int nf = 0; nf < 4; ++nf) {                                          \
        sa[nf][0] = sa_n[nf][0]; sa[nf][1] = sa_n[nf][1];                     \
        sa[nf][2] = sa_n[nf][2]; sa[nf][3] = sa_n[nf][3];                     \
    }                                                                         \
} while (0)

    // sa = S(tile 0)
    S_MMA(sa, 0);

    int t = 0;
#pragma unroll 1
    for (int i = 0; i < 21; ++i) {
        ITER(t, 0, 1, 2); ++t;
        ITER(t, 1, 2, 0); ++t;
        ITER(t, 2, 0, 1); ++t;
    }
    // epilogue: tile 63, buffer 0 (copied at ITER(61), waited+synced at ITER(62))
    SOFTMAX_PV(0);

#undef ITER
#undef SOFTMAX_PV
#undef S_MMA

    // ---- normalize + store ----
    {
        float iA = 1.f / lrA, iB = 1.f / lrB;
        float* o0 = out + (size_t)(b * LQ + q0 + warp * 16 + g) * (NH * DK) + h * DK;
        float* o1 = o0 + (size_t)8 * (NH * DK);
#pragma unroll
        for (int nf = 0; nf < 8; ++nf) {
            int c = (nf >> 1) * 16 + (nf & 1) * 8 + 2 * tg;
            *(float2*)(o0 + c) = make_float2(o[nf][0] * iA, o[nf][1] * iA);
            *(float2*)(o1 + c) = make_float2(o[nf][2] * iB, o[nf][3] * iB);
        }
    }
}

// ---------------------------------------------------------------------------
extern "C" void kernel_launch(void* const* d_in, const int* in_sizes, int n_in,
                              void* d_out, int out_size)
{
    const float* Q    = (const float*)d_in[0];
    const float* K    = (const float*)d_in[1];
    const float* V    = (const float*)d_in[2];
    const int*   mask = (const int*)d_in[3];
    const float* Wq   = (const float*)d_in[4];
    const float* bq   = (const float*)d_in[5];
    const float* Wk   = (const float*)d_in[6];
    const float* Wv   = (const float*)d_in[7];
    const float* bv   = (const float*)d_in[8];
    float* out = (float*)d_out;

    cudaFuncSetAttribute(attn_pipe, cudaFuncAttributeMaxDynamicSharedMemorySize,
                         ATTN_SMEM);

    dim3 gproj((NH * DK) / 64, (BB * LQ) / 128, 3);  // (16, 64, 3)
    proj_hmma<<<gproj, 256>>>(Q, K, V, Wq, bq, Wk, Wv, bv);

    dim3 gattn(LQ / 128, NH, BB);  // (16, 16, 4)
    attn_pipe<<<gattn, 256, ATTN_SMEM>>>(mask, out);
}